// round 13
// baseline (speedup 1.0000x reference)
#include <cuda_runtime.h>
#include <cuda_fp16.h>
#include <cstdint>

#define D_DIM 128
#define MAX_NODES 100000

// Per-node projections in fp16: row n = [P(16 half) | Q(16 half)] = 64 bytes.
// 6.4 MB -> L2-resident. Error: fp16 GEMM ~2.5e-4 + fp16 PQ ~2.1e-4 => ~3.6e-4
// measured, 3x under the 1e-3 threshold.
__device__ __half g_PQh[(size_t)MAX_NODES * 32];
__device__ int g_idx64;

// m16n8k16 fp16 HMMA, fp32 accumulate (sm_80+; compiles on plain sm_100).
__device__ __forceinline__ void mma16816(float* c, uint32_t a0, uint32_t a1,
                                         uint32_t a2, uint32_t a3,
                                         uint32_t b0, uint32_t b1) {
    asm volatile(
        "mma.sync.aligned.m16n8k16.row.col.f32.f16.f16.f32 "
        "{%0,%1,%2,%3}, {%4,%5,%6,%7}, {%8,%9}, {%0,%1,%2,%3};"
        : "+f"(c[0]), "+f"(c[1]), "+f"(c[2]), "+f"(c[3])
        : "r"(a0), "r"(a1), "r"(a2), "r"(a3), "r"(b0), "r"(b1));
}

__device__ __forceinline__ uint32_t packh2(float a, float b) {
    __half2 p = __floats2half2_rn(a, b);   // .x = a (low 16)
    return *reinterpret_cast<uint32_t*>(&p);
}

#define PAD 68    // u32 row stride (64 + 4): (row*68 + 4*gid + tid4) conflict-free
// smem: sA [128][68] u32 then sW [32][68] u32 -> 160*68*4 = 43,520 B
#define SM_W (128 * PAD)
#define SMEM_BYTES (160 * PAD * 4)

// ---------------------------------------------------------------------------
// Detect int64 vs int32 edge indices (ids < 100k => int64 odd words all zero;
// int32 random ids false-positive ~1e-160). Placed BETWEEN precompute and
// gather in the stream so the profiled slot lands on precompute.
// ---------------------------------------------------------------------------
__global__ void detect_idx_kernel(const int* __restrict__ src_words) {
    int ok = (src_words[threadIdx.x * 2 + 1] == 0);
    int all = __all_sync(0xffffffffu, ok);
    if (threadIdx.x == 0) g_idx64 = all;
}

// ---------------------------------------------------------------------------
// Kernel 1: PQ = GEMM [node tile x 32 cols x K=128], single-pass fp16 HMMA
// with fp32 accumulation. 256 threads; warp w owns rows 16w..16w+15 of the
// current tile x all 32 cols. Each block processes TWO 128-node tiles,
// staging W once. __launch_bounds__(256, 5): cap regs (~51) so occupancy is
// smem-limited (5 CTAs/SM, 40 warps) instead of register-limited (3 CTAs) —
// R12 profile showed occ 33%, regs 78, nothing saturated = latency-bound.
// ---------------------------------------------------------------------------
__global__ __launch_bounds__(256, 5) void precompute_kernel(const float* __restrict__ h,
                                                            const float* __restrict__ W,
                                                            const float* __restrict__ b,
                                                            int n_nodes) {
    extern __shared__ uint32_t smem[];
    uint32_t* sA = smem;          // [row][kpair] fp16x2
    uint32_t* sW = smem + SM_W;   // [out col][kpair] fp16x2

    const int t = threadIdx.x;
    const int warp = t >> 5;
    const int lane = t & 31;
    const int gid = lane >> 2;    // fragment group 0..7
    const int tid4 = lane & 3;    // 0..3

    // ---- stage W once (full K): col j<16 -> W_s row j ; j>=16 -> W_d row j-16.
#pragma unroll
    for (int s = 0; s < 4; s++) {
        int idx = s * 256 + t;
        int col = idx >> 5;        // 0..31
        int f4 = idx & 31;         // float4 within 128 k-values
        float4 wv = *reinterpret_cast<const float4*>(
            W + (size_t)(col & 15) * 256 + ((col >> 4) << 7) + f4 * 4);
        *reinterpret_cast<uint2*>(&sW[col * PAD + f4 * 2]) =
            make_uint2(packh2(wv.x, wv.y), packh2(wv.z, wv.w));
    }

#pragma unroll
    for (int tile = 0; tile < 2; tile++) {
        const int n0 = blockIdx.x * 256 + tile * 128;
        if (n0 >= n_nodes) break;
        if (tile) __syncthreads();   // previous tile's MMA reads must finish

        // ---- stage A (full K): each warp covers one full row (512B) per step.
#pragma unroll
        for (int s = 0; s < 16; s++) {
            int idx = s * 256 + t;
            int row = idx >> 5;        // 0..127
            int f4 = idx & 31;
            int n = n0 + row;
            if (n > n_nodes - 1) n = n_nodes - 1;
            float4 v = *reinterpret_cast<const float4*>(h + (size_t)n * D_DIM + f4 * 4);
            *reinterpret_cast<uint2*>(&sA[row * PAD + f4 * 2]) =
                make_uint2(packh2(v.x, v.y), packh2(v.z, v.w));
        }
        __syncthreads();

        // ---- MMA: 8 k16 steps x 4 n8 tiles = 32 HMMA per warp.
        float acc[4][4];
#pragma unroll
        for (int nt = 0; nt < 4; nt++)
#pragma unroll
            for (int q = 0; q < 4; q++) acc[nt][q] = 0.f;

#pragma unroll
        for (int ks = 0; ks < 8; ks++) {
            const int kb = ks * 8 + tid4;
            int r0 = (warp * 16 + gid) * PAD + kb;
            int r1 = r0 + 8 * PAD;
            uint32_t a0 = sA[r0], a1 = sA[r1], a2 = sA[r0 + 4], a3 = sA[r1 + 4];
#pragma unroll
            for (int nt = 0; nt < 4; nt++) {
                int base = (nt * 8 + gid) * PAD + kb;
                mma16816(acc[nt], a0, a1, a2, a3, sW[base], sW[base + 4]);
            }
        }

        // ---- epilogue: c0,c1 -> row gid, c2,c3 -> row gid+8; bias cols<16.
#pragma unroll
        for (int nt = 0; nt < 4; nt++) {
            int col = nt * 8 + 2 * tid4;
            float2 bias = make_float2(0.f, 0.f);
            if (nt < 2) bias = *reinterpret_cast<const float2*>(b + col);
            int row0 = n0 + warp * 16 + gid;
            if (row0 < n_nodes)
                *reinterpret_cast<__half2*>(g_PQh + (size_t)row0 * 32 + col) =
                    __floats2half2_rn(acc[nt][0] + bias.x, acc[nt][1] + bias.y);
            if (row0 + 8 < n_nodes)
                *reinterpret_cast<__half2*>(g_PQh + (size_t)(row0 + 8) * 32 + col) =
                    __floats2half2_rn(acc[nt][2] + bias.x, acc[nt][3] + bias.y);
        }
    }
}

// ---------------------------------------------------------------------------
// Kernel 2 (unchanged, 31.0us proven): out[e][c] = Ph[src[e]][c] + Qh[dst[e]][c].
// 4 lanes/edge, 8B gathers (P row = 1 sector), contiguous float4 stores,
// 64 edges/warp, all 8 gather loads batched before processing.
// ---------------------------------------------------------------------------
__global__ __launch_bounds__(256) void gather_kernel(const void* __restrict__ src_raw,
                                                     const void* __restrict__ dst_raw,
                                                     float* __restrict__ out,
                                                     int n_edges) {
    const int lane = threadIdx.x & 31;
    const long long wid = (long long)blockIdx.x * (blockDim.x >> 5) + (threadIdx.x >> 5);
    const long long e0 = wid * 64;
    if (e0 >= n_edges) return;

    long long ea = e0 + lane, eb = e0 + 32 + lane;
    if (ea > n_edges - 1) ea = n_edges - 1;
    if (eb > n_edges - 1) eb = n_edges - 1;

    int s0, s1, d0, d1;
    if (g_idx64) {
        s0 = (int)__ldcs(reinterpret_cast<const long long*>(src_raw) + ea);
        s1 = (int)__ldcs(reinterpret_cast<const long long*>(src_raw) + eb);
        d0 = (int)__ldcs(reinterpret_cast<const long long*>(dst_raw) + ea);
        d1 = (int)__ldcs(reinterpret_cast<const long long*>(dst_raw) + eb);
    } else {
        s0 = __ldcs(reinterpret_cast<const int*>(src_raw) + ea);
        s1 = __ldcs(reinterpret_cast<const int*>(src_raw) + eb);
        d0 = __ldcs(reinterpret_cast<const int*>(dst_raw) + ea);
        d1 = __ldcs(reinterpret_cast<const int*>(dst_raw) + eb);
    }

    const int sub = lane >> 2;    // edge-in-group 0..7
    const int comp = lane & 3;    // 4-half (8B) chunk within 16-half row

#pragma unroll
    for (int half = 0; half < 2; half++) {
        const int sv = half ? s1 : s0;
        const int dv = half ? d1 : d0;
        const long long ebase = e0 + half * 32 + sub;

        // Phase 1: issue all 8 gather loads (clamped idx -> always safe).
        uint2 pv[4], qv[4];
#pragma unroll
        for (int g = 0; g < 4; g++) {
            int se = __shfl_sync(0xffffffffu, sv, g * 8 + sub);
            int de = __shfl_sync(0xffffffffu, dv, g * 8 + sub);
            pv[g] = __ldcg(reinterpret_cast<const uint2*>(
                g_PQh + (size_t)se * 32) + comp);
            qv[g] = __ldcg(reinterpret_cast<const uint2*>(
                g_PQh + (size_t)de * 32 + 16) + comp);
        }

        // Phase 2: convert, add, guarded contiguous float4 store.
#pragma unroll
        for (int g = 0; g < 4; g++) {
            long long eg = ebase + g * 8;
            if (eg < n_edges) {
                __half2 p0 = *reinterpret_cast<const __half2*>(&pv[g].x);
                __half2 p1 = *reinterpret_cast<const __half2*>(&pv[g].y);
                __half2 q0 = *reinterpret_cast<const __half2*>(&qv[g].x);
                __half2 q1 = *reinterpret_cast<const __half2*>(&qv[g].y);
                float2 a0 = __half22float2(p0), c0 = __half22float2(q0);
                float2 a1 = __half22float2(p1), c1 = __half22float2(q1);
                float4 r = make_float4(a0.x + c0.x, a0.y + c0.y,
                                       a1.x + c1.x, a1.y + c1.y);
                __stcs(reinterpret_cast<float4*>(out) + eg * 4 + comp, r);
            }
        }
    }
}

// ---------------------------------------------------------------------------
// Inputs (metadata order): h [N*128 f32], src [E idx], dst [E idx],
//                          W [16*256 f32], b [16 f32]. Output: [E*16 f32].
// Launch order (pre, detect, gather): detect only gates gather; placing it
// second keeps precompute in the ncu-profiled slot.
// ---------------------------------------------------------------------------
extern "C" void kernel_launch(void* const* d_in, const int* in_sizes, int n_in,
                              void* d_out, int out_size) {
    const float* h = (const float*)d_in[0];
    const void* src = d_in[1];
    const void* dst = d_in[2];
    const float* W = (const float*)d_in[3];
    const float* b = (const float*)d_in[4];

    int n_nodes = in_sizes[0] / D_DIM;
    int n_edges = in_sizes[1];

    cudaFuncSetAttribute(precompute_kernel,
                         cudaFuncAttributeMaxDynamicSharedMemorySize, SMEM_BYTES);

    int blocks1 = (n_nodes + 255) / 256;   // 2 tiles per block
    precompute_kernel<<<blocks1, 256, SMEM_BYTES>>>(h, W, b, n_nodes);

    detect_idx_kernel<<<1, 32>>>((const int*)src);

    long long warps = ((long long)n_edges + 63) / 64;
    int blocks2 = (int)((warps + 7) / 8);
    gather_kernel<<<blocks2, 256>>>(src, dst, (float*)d_out, n_edges);
}

// round 14
// speedup vs baseline: 1.0981x; 1.0981x over previous
#include <cuda_runtime.h>
#include <cuda_fp16.h>
#include <cstdint>

#define D_DIM 128
#define MAX_NODES 100000

// Per-node projections in fp16: row n = [P(16 half) | Q(16 half)] = 64 bytes.
// 6.4 MB -> L2-resident. Error: fp16 GEMM ~2.5e-4 + fp16 PQ ~2.1e-4 => 3.6e-4
// measured, ~3x under the 1e-3 threshold.
__device__ __half g_PQh[(size_t)MAX_NODES * 32];
__device__ int g_idx64;

// m16n8k16 fp16 HMMA, fp32 accumulate (sm_80+; compiles on plain sm_100).
__device__ __forceinline__ void mma16816(float* c, uint32_t a0, uint32_t a1,
                                         uint32_t a2, uint32_t a3,
                                         uint32_t b0, uint32_t b1) {
    asm volatile(
        "mma.sync.aligned.m16n8k16.row.col.f32.f16.f16.f32 "
        "{%0,%1,%2,%3}, {%4,%5,%6,%7}, {%8,%9}, {%0,%1,%2,%3};"
        : "+f"(c[0]), "+f"(c[1]), "+f"(c[2]), "+f"(c[3])
        : "r"(a0), "r"(a1), "r"(a2), "r"(a3), "r"(b0), "r"(b1));
}

__device__ __forceinline__ uint32_t packh2(float a, float b) {
    __half2 p = __floats2half2_rn(a, b);   // .x = a (low 16)
    return *reinterpret_cast<uint32_t*>(&p);
}

#define PAD 68    // u32 row stride (64 + 4): (row*68 + 4*gid + tid4) conflict-free
// smem: sA [128][68] u32 then sW [32][68] u32 -> 160*68*4 = 43,520 B
#define SM_W (128 * PAD)
#define SMEM_BYTES (160 * PAD * 4)

// ---------------------------------------------------------------------------
// Detect int64 vs int32 edge indices (ids < 100k => int64 odd words all zero;
// int32 random ids false-positive ~1e-160). Middle launch slot -> ncu
// profiles precompute.
// ---------------------------------------------------------------------------
__global__ void detect_idx_kernel(const int* __restrict__ src_words) {
    int ok = (src_words[threadIdx.x * 2 + 1] == 0);
    int all = __all_sync(0xffffffffu, ok);
    if (threadIdx.x == 0) g_idx64 = all;
}

// ---------------------------------------------------------------------------
// Kernel 1 (R11 single-tile structure, grid 782): PQ = [128-node tile x
// 32 cols x K=128] GEMM, single-pass fp16 HMMA + fp32 accum. 256 threads;
// warp w owns rows 16w..16w+15 x all 32 cols. Full K staged once.
// __launch_bounds__(256, 4): at grid 782 occupancy IS register-limited
// (78 regs -> 3 CTAs/SM); cap at 64 regs -> 4 CTAs/SM without touching the
// 16 accumulators (single-tile kernel has slack in address math).
// ---------------------------------------------------------------------------
__global__ __launch_bounds__(256, 4) void precompute_kernel(const float* __restrict__ h,
                                                            const float* __restrict__ W,
                                                            const float* __restrict__ b,
                                                            int n_nodes) {
    extern __shared__ uint32_t smem[];
    uint32_t* sA = smem;          // [row][kpair] fp16x2
    uint32_t* sW = smem + SM_W;   // [out col][kpair] fp16x2

    const int t = threadIdx.x;
    const int warp = t >> 5;
    const int lane = t & 31;
    const int gid = lane >> 2;    // fragment group 0..7
    const int tid4 = lane & 3;    // 0..3

    const int n0 = blockIdx.x * 128;

    // ---- stage W (full K): out col j<16 -> W_s row j ; j>=16 -> W_d row j-16.
#pragma unroll
    for (int s = 0; s < 4; s++) {
        int idx = s * 256 + t;
        int col = idx >> 5;        // 0..31
        int f4 = idx & 31;         // float4 within 128 k-values
        float4 wv = *reinterpret_cast<const float4*>(
            W + (size_t)(col & 15) * 256 + ((col >> 4) << 7) + f4 * 4);
        *reinterpret_cast<uint2*>(&sW[col * PAD + f4 * 2]) =
            make_uint2(packh2(wv.x, wv.y), packh2(wv.z, wv.w));
    }

    // ---- stage A (full K): each warp covers one full row (512B) per step.
#pragma unroll
    for (int s = 0; s < 16; s++) {
        int idx = s * 256 + t;
        int row = idx >> 5;        // 0..127
        int f4 = idx & 31;
        int n = n0 + row;
        if (n > n_nodes - 1) n = n_nodes - 1;
        float4 v = *reinterpret_cast<const float4*>(h + (size_t)n * D_DIM + f4 * 4);
        *reinterpret_cast<uint2*>(&sA[row * PAD + f4 * 2]) =
            make_uint2(packh2(v.x, v.y), packh2(v.z, v.w));
    }
    __syncthreads();

    // ---- MMA: 8 k16 steps x 4 n8 tiles = 32 HMMA per warp, single pass.
    float acc[4][4];
#pragma unroll
    for (int nt = 0; nt < 4; nt++)
#pragma unroll
        for (int q = 0; q < 4; q++) acc[nt][q] = 0.f;

#pragma unroll
    for (int ks = 0; ks < 8; ks++) {
        const int kb = ks * 8 + tid4;
        int r0 = (warp * 16 + gid) * PAD + kb;
        int r1 = r0 + 8 * PAD;
        uint32_t a0 = sA[r0], a1 = sA[r1], a2 = sA[r0 + 4], a3 = sA[r1 + 4];
#pragma unroll
        for (int nt = 0; nt < 4; nt++) {
            int base = (nt * 8 + gid) * PAD + kb;
            mma16816(acc[nt], a0, a1, a2, a3, sW[base], sW[base + 4]);
        }
    }

    // ---- epilogue: c0,c1 -> row gid, c2,c3 -> row gid+8; bias on cols<16.
#pragma unroll
    for (int nt = 0; nt < 4; nt++) {
        int col = nt * 8 + 2 * tid4;
        float2 bias = make_float2(0.f, 0.f);
        if (nt < 2) bias = *reinterpret_cast<const float2*>(b + col);
        int row0 = n0 + warp * 16 + gid;
        if (row0 < n_nodes)
            *reinterpret_cast<__half2*>(g_PQh + (size_t)row0 * 32 + col) =
                __floats2half2_rn(acc[nt][0] + bias.x, acc[nt][1] + bias.y);
        if (row0 + 8 < n_nodes)
            *reinterpret_cast<__half2*>(g_PQh + (size_t)(row0 + 8) * 32 + col) =
                __floats2half2_rn(acc[nt][2] + bias.x, acc[nt][3] + bias.y);
    }
}

// ---------------------------------------------------------------------------
// Kernel 2 (unchanged, 31.0us proven): out[e][c] = Ph[src[e]][c] + Qh[dst[e]][c].
// 4 lanes/edge, 8B gathers (P row = 1 sector), contiguous float4 stores,
// 64 edges/warp, all 8 gather loads batched before processing.
// ---------------------------------------------------------------------------
__global__ __launch_bounds__(256) void gather_kernel(const void* __restrict__ src_raw,
                                                     const void* __restrict__ dst_raw,
                                                     float* __restrict__ out,
                                                     int n_edges) {
    const int lane = threadIdx.x & 31;
    const long long wid = (long long)blockIdx.x * (blockDim.x >> 5) + (threadIdx.x >> 5);
    const long long e0 = wid * 64;
    if (e0 >= n_edges) return;

    long long ea = e0 + lane, eb = e0 + 32 + lane;
    if (ea > n_edges - 1) ea = n_edges - 1;
    if (eb > n_edges - 1) eb = n_edges - 1;

    int s0, s1, d0, d1;
    if (g_idx64) {
        s0 = (int)__ldcs(reinterpret_cast<const long long*>(src_raw) + ea);
        s1 = (int)__ldcs(reinterpret_cast<const long long*>(src_raw) + eb);
        d0 = (int)__ldcs(reinterpret_cast<const long long*>(dst_raw) + ea);
        d1 = (int)__ldcs(reinterpret_cast<const long long*>(dst_raw) + eb);
    } else {
        s0 = __ldcs(reinterpret_cast<const int*>(src_raw) + ea);
        s1 = __ldcs(reinterpret_cast<const int*>(src_raw) + eb);
        d0 = __ldcs(reinterpret_cast<const int*>(dst_raw) + ea);
        d1 = __ldcs(reinterpret_cast<const int*>(dst_raw) + eb);
    }

    const int sub = lane >> 2;    // edge-in-group 0..7
    const int comp = lane & 3;    // 4-half (8B) chunk within 16-half row

#pragma unroll
    for (int half = 0; half < 2; half++) {
        const int sv = half ? s1 : s0;
        const int dv = half ? d1 : d0;
        const long long ebase = e0 + half * 32 + sub;

        // Phase 1: issue all 8 gather loads (clamped idx -> always safe).
        uint2 pv[4], qv[4];
#pragma unroll
        for (int g = 0; g < 4; g++) {
            int se = __shfl_sync(0xffffffffu, sv, g * 8 + sub);
            int de = __shfl_sync(0xffffffffu, dv, g * 8 + sub);
            pv[g] = __ldcg(reinterpret_cast<const uint2*>(
                g_PQh + (size_t)se * 32) + comp);
            qv[g] = __ldcg(reinterpret_cast<const uint2*>(
                g_PQh + (size_t)de * 32 + 16) + comp);
        }

        // Phase 2: convert, add, guarded contiguous float4 store.
#pragma unroll
        for (int g = 0; g < 4; g++) {
            long long eg = ebase + g * 8;
            if (eg < n_edges) {
                __half2 p0 = *reinterpret_cast<const __half2*>(&pv[g].x);
                __half2 p1 = *reinterpret_cast<const __half2*>(&pv[g].y);
                __half2 q0 = *reinterpret_cast<const __half2*>(&qv[g].x);
                __half2 q1 = *reinterpret_cast<const __half2*>(&qv[g].y);
                float2 a0 = __half22float2(p0), c0 = __half22float2(q0);
                float2 a1 = __half22float2(p1), c1 = __half22float2(q1);
                float4 r = make_float4(a0.x + c0.x, a0.y + c0.y,
                                       a1.x + c1.x, a1.y + c1.y);
                __stcs(reinterpret_cast<float4*>(out) + eg * 4 + comp, r);
            }
        }
    }
}

// ---------------------------------------------------------------------------
// Inputs (metadata order): h [N*128 f32], src [E idx], dst [E idx],
//                          W [16*256 f32], b [16 f32]. Output: [E*16 f32].
// ---------------------------------------------------------------------------
extern "C" void kernel_launch(void* const* d_in, const int* in_sizes, int n_in,
                              void* d_out, int out_size) {
    const float* h = (const float*)d_in[0];
    const void* src = d_in[1];
    const void* dst = d_in[2];
    const float* W = (const float*)d_in[3];
    const float* b = (const float*)d_in[4];

    int n_nodes = in_sizes[0] / D_DIM;
    int n_edges = in_sizes[1];

    cudaFuncSetAttribute(precompute_kernel,
                         cudaFuncAttributeMaxDynamicSharedMemorySize, SMEM_BYTES);

    int blocks1 = (n_nodes + 127) / 128;   // single tile per block, grid 782
    precompute_kernel<<<blocks1, 256, SMEM_BYTES>>>(h, W, b, n_nodes);

    detect_idx_kernel<<<1, 32>>>((const int*)src);

    long long warps = ((long long)n_edges + 63) / 64;
    int blocks2 = (int)((warps + 7) / 8);
    gather_kernel<<<blocks2, 256>>>(src, dst, (float*)d_out, n_edges);
}